// round 1
// baseline (speedup 1.0000x reference)
#include <cuda_runtime.h>
#include <cstddef>

#define LTOK 4096   // H*W tokens
#define CCH  512    // in channels
#define CIN  256    // inter channels
#define NBAT 4      // batch
#define EPSV 1e-5f

// ---------------- scratch (device globals: no runtime allocation) ----------
__device__ float d_theta[(size_t)NBAT * CIN * LTOK];
__device__ float d_phi  [(size_t)NBAT * CIN * LTOK];
__device__ float d_gbuf [(size_t)NBAT * CIN * LTOK];
__device__ float d_f    [(size_t)NBAT * LTOK * LTOK];   // 268 MB attention logits
__device__ float d_y2   [(size_t)NBAT * LTOK * CIN];    // y as (L, CI) per batch
__device__ float d_wy   [(size_t)NBAT * CCH * LTOK];
__device__ float d_mean [CCH];
__device__ float d_rstd [CCH];

// ---------------- generic 128x128x16 register-tiled SGEMM ------------------
// C[m,n] = sum_k A(m,k) * B(k,n) (+ bias[m])
//   TA=false: A row-major M x K, lda = K-stride        A[m*lda + k]
//   TA=true : A stored K x M,    lda = M-stride        A[k*lda + m]
//   TB=false: B row-major K x N, ldb                   B[k*ldb + n]
//   TB=true : B stored N x K,    ldb                   B[n*ldb + k]
// blockIdx.z selects batch via element strides sA/sB/sC.
// All of M, N divisible by 128; K divisible by 16 (true for every call here).
constexpr int BM = 128, BN = 128, BK = 16;

template<bool TA, bool TB, bool BIAS>
__global__ __launch_bounds__(256)
void sgemm_kernel(const float* __restrict__ A, int lda, long long sA,
                  const float* __restrict__ B, int ldb, long long sB,
                  float*       __restrict__ C, int ldc, long long sC,
                  const float* __restrict__ bias,
                  int M, int N, int K)
{
    A += (size_t)blockIdx.z * sA;
    B += (size_t)blockIdx.z * sB;
    C += (size_t)blockIdx.z * sC;

    const int bm = blockIdx.y * BM;
    const int bn = blockIdx.x * BN;
    const int tid = threadIdx.x;
    const int tx = tid & 15;      // 16 cols of threads
    const int ty = tid >> 4;      // 16 rows of threads

    __shared__ float As[BK][BM + 4];
    __shared__ float Bs[BK][BN + 4];

    float acc[8][8];
#pragma unroll
    for (int i = 0; i < 8; i++)
#pragma unroll
        for (int j = 0; j < 8; j++) acc[i][j] = 0.f;

    for (int kt = 0; kt < K; kt += BK) {
        // ---- load A tile into As[k][m] ----
        if (!TA) {
            // A row-major: rows bm..bm+127, cols kt..kt+15 -> transpose into As
            const int arow = tid >> 2;            // 0..63
            const int acol = (tid & 3) * 4;       // 0,4,8,12
#pragma unroll
            for (int r = 0; r < 2; r++) {
                const float4 v = *(const float4*)&A[(size_t)(bm + arow + r * 64) * lda + kt + acol];
                As[acol + 0][arow + r * 64] = v.x;
                As[acol + 1][arow + r * 64] = v.y;
                As[acol + 2][arow + r * 64] = v.z;
                As[acol + 3][arow + r * 64] = v.w;
            }
        } else {
            // A stored K x M: direct copy
            const int krow = tid >> 5;            // 0..7
            const int mcol = (tid & 31) * 4;      // 0..124
#pragma unroll
            for (int r = 0; r < 2; r++) {
                const float4 v = *(const float4*)&A[(size_t)(kt + krow + r * 8) * lda + bm + mcol];
                *(float4*)&As[krow + r * 8][mcol] = v;
            }
        }
        // ---- load B tile into Bs[k][n] ----
        if (!TB) {
            const int krow = tid >> 5;
            const int ncol = (tid & 31) * 4;
#pragma unroll
            for (int r = 0; r < 2; r++) {
                const float4 v = *(const float4*)&B[(size_t)(kt + krow + r * 8) * ldb + bn + ncol];
                *(float4*)&Bs[krow + r * 8][ncol] = v;
            }
        } else {
            // B stored N x K: transpose into Bs
            const int nrow = tid >> 2;
            const int kcol = (tid & 3) * 4;
#pragma unroll
            for (int r = 0; r < 2; r++) {
                const float4 v = *(const float4*)&B[(size_t)(bn + nrow + r * 64) * ldb + kt + kcol];
                Bs[kcol + 0][nrow + r * 64] = v.x;
                Bs[kcol + 1][nrow + r * 64] = v.y;
                Bs[kcol + 2][nrow + r * 64] = v.z;
                Bs[kcol + 3][nrow + r * 64] = v.w;
            }
        }
        __syncthreads();

#pragma unroll
        for (int k = 0; k < BK; k++) {
            float a[8], b[8];
            *(float4*)&a[0] = *(const float4*)&As[k][ty * 4];
            *(float4*)&a[4] = *(const float4*)&As[k][ty * 4 + 64];
            *(float4*)&b[0] = *(const float4*)&Bs[k][tx * 4];
            *(float4*)&b[4] = *(const float4*)&Bs[k][tx * 4 + 64];
#pragma unroll
            for (int i = 0; i < 8; i++)
#pragma unroll
                for (int j = 0; j < 8; j++)
                    acc[i][j] = fmaf(a[i], b[j], acc[i][j]);
        }
        __syncthreads();
    }

    // ---- epilogue ----
#pragma unroll
    for (int i = 0; i < 8; i++) {
        const int row = bm + ((i < 4) ? (ty * 4 + i) : (64 + ty * 4 + (i - 4)));
        float bv = 0.f;
        if (BIAS) bv = bias[row];
        float4 o0, o1;
        o0.x = acc[i][0] + bv; o0.y = acc[i][1] + bv;
        o0.z = acc[i][2] + bv; o0.w = acc[i][3] + bv;
        o1.x = acc[i][4] + bv; o1.y = acc[i][5] + bv;
        o1.z = acc[i][6] + bv; o1.w = acc[i][7] + bv;
        *(float4*)&C[(size_t)row * ldc + bn + tx * 4]      = o0;
        *(float4*)&C[(size_t)row * ldc + bn + tx * 4 + 64] = o1;
    }
}

// ---------------- row softmax over f (rows of 4096) -------------------------
__global__ __launch_bounds__(256)
void softmax_kernel(float* __restrict__ f)
{
    float* row = f + (size_t)blockIdx.x * LTOK;
    const int tid = threadIdx.x;

    float4 v[4];
    float m = -1e30f;
#pragma unroll
    for (int i = 0; i < 4; i++) {
        v[i] = *(const float4*)&row[tid * 4 + i * 1024];
        m = fmaxf(m, fmaxf(fmaxf(v[i].x, v[i].y), fmaxf(v[i].z, v[i].w)));
    }
#pragma unroll
    for (int o = 16; o; o >>= 1) m = fmaxf(m, __shfl_xor_sync(0xffffffffu, m, o));

    __shared__ float red[8];
    if ((tid & 31) == 0) red[tid >> 5] = m;
    __syncthreads();
    float gmax = -1e30f;
#pragma unroll
    for (int i = 0; i < 8; i++) gmax = fmaxf(gmax, red[i]);

    float s = 0.f;
#pragma unroll
    for (int i = 0; i < 4; i++) {
        v[i].x = __expf(v[i].x - gmax);
        v[i].y = __expf(v[i].y - gmax);
        v[i].z = __expf(v[i].z - gmax);
        v[i].w = __expf(v[i].w - gmax);
        s += v[i].x + v[i].y + v[i].z + v[i].w;
    }
#pragma unroll
    for (int o = 16; o; o >>= 1) s += __shfl_xor_sync(0xffffffffu, s, o);
    __syncthreads();
    if ((tid & 31) == 0) red[tid >> 5] = s;
    __syncthreads();
    float gsum = 0.f;
#pragma unroll
    for (int i = 0; i < 8; i++) gsum += red[i];
    const float inv = 1.f / gsum;

#pragma unroll
    for (int i = 0; i < 4; i++) {
        v[i].x *= inv; v[i].y *= inv; v[i].z *= inv; v[i].w *= inv;
        *(float4*)&row[tid * 4 + i * 1024] = v[i];
    }
}

// ---------------- batchnorm statistics (per channel over N,H,W) -------------
__global__ __launch_bounds__(256)
void bn_stats_kernel(const float* __restrict__ wy,
                     float* __restrict__ mean, float* __restrict__ rstd)
{
    const int c = blockIdx.x;
    float s = 0.f, s2 = 0.f;
    for (int idx = threadIdx.x; idx < NBAT * LTOK; idx += 256) {
        const int n = idx >> 12;
        const int l = idx & (LTOK - 1);
        const float v = wy[((size_t)n * CCH + c) * LTOK + l];
        s += v; s2 += v * v;
    }
#pragma unroll
    for (int o = 16; o; o >>= 1) {
        s  += __shfl_xor_sync(0xffffffffu, s, o);
        s2 += __shfl_xor_sync(0xffffffffu, s2, o);
    }
    __shared__ float rs[8], rs2[8];
    if ((threadIdx.x & 31) == 0) { rs[threadIdx.x >> 5] = s; rs2[threadIdx.x >> 5] = s2; }
    __syncthreads();
    if (threadIdx.x == 0) {
        float S = 0.f, S2 = 0.f;
#pragma unroll
        for (int i = 0; i < 8; i++) { S += rs[i]; S2 += rs2[i]; }
        const float inv_cnt = 1.f / (float)(NBAT * LTOK);
        const float mu = S * inv_cnt;
        const float var = S2 * inv_cnt - mu * mu;
        mean[c] = mu;
        rstd[c] = rsqrtf(var + EPSV);
    }
}

// ---------------- BN apply + residual ---------------------------------------
__global__ __launch_bounds__(256)
void bn_apply_kernel(const float* __restrict__ wy, const float* __restrict__ x,
                     const float* __restrict__ gamma, const float* __restrict__ beta,
                     const float* __restrict__ mean, const float* __restrict__ rstd,
                     float* __restrict__ out)
{
    const size_t i = (size_t)blockIdx.x * blockDim.x + threadIdx.x;
    const size_t base = i * 4;
    if (base >= (size_t)NBAT * CCH * LTOK) return;
    const int c = (int)((base >> 12) & (CCH - 1));
    const float4 w  = *(const float4*)(wy + base);
    const float4 xv = *(const float4*)(x + base);
    const float mu = mean[c];
    const float sc = rstd[c] * gamma[c];
    const float be = beta[c];
    float4 o;
    o.x = (w.x - mu) * sc + be + xv.x;
    o.y = (w.y - mu) * sc + be + xv.y;
    o.z = (w.z - mu) * sc + be + xv.z;
    o.w = (w.w - mu) * sc + be + xv.w;
    *(float4*)(out + base) = o;
}

// ---------------- launch ------------------------------------------------------
extern "C" void kernel_launch(void* const* d_in, const int* in_sizes, int n_in,
                              void* d_out, int out_size)
{
    const float* x     = (const float*)d_in[0];
    const float* g_w   = (const float*)d_in[1];
    const float* g_b   = (const float*)d_in[2];
    const float* th_w  = (const float*)d_in[3];
    const float* th_b  = (const float*)d_in[4];
    const float* ph_w  = (const float*)d_in[5];
    const float* ph_b  = (const float*)d_in[6];
    const float* wz_w  = (const float*)d_in[7];
    const float* wz_b  = (const float*)d_in[8];
    const float* gamma = (const float*)d_in[9];
    const float* beta  = (const float*)d_in[10];
    float* out = (float*)d_out;

    float *p_theta, *p_phi, *p_g, *p_f, *p_y2, *p_wy, *p_mean, *p_rstd;
    cudaGetSymbolAddress((void**)&p_theta, d_theta);
    cudaGetSymbolAddress((void**)&p_phi,   d_phi);
    cudaGetSymbolAddress((void**)&p_g,     d_gbuf);
    cudaGetSymbolAddress((void**)&p_f,     d_f);
    cudaGetSymbolAddress((void**)&p_y2,    d_y2);
    cudaGetSymbolAddress((void**)&p_wy,    d_wy);
    cudaGetSymbolAddress((void**)&p_mean,  d_mean);
    cudaGetSymbolAddress((void**)&p_rstd,  d_rstd);

    const dim3 blk(256);
    const long long sX  = (long long)CCH * LTOK;   // x batch stride
    const long long sP  = (long long)CIN * LTOK;   // projection batch stride
    const long long sF  = (long long)LTOK * LTOK;  // f batch stride
    const long long sY  = (long long)LTOK * CIN;   // y2 batch stride
    const long long sW  = (long long)CCH * LTOK;   // wy batch stride

    // 1) projections: theta/phi/g = W(CI x C) @ x(C x L) + b   per batch
    {
        dim3 g(LTOK / BN, CIN / BM, NBAT);
        sgemm_kernel<false, false, true><<<g, blk>>>(th_w, CCH, 0, x, LTOK, sX,
                                                     p_theta, LTOK, sP, th_b,
                                                     CIN, LTOK, CCH);
        sgemm_kernel<false, false, true><<<g, blk>>>(ph_w, CCH, 0, x, LTOK, sX,
                                                     p_phi, LTOK, sP, ph_b,
                                                     CIN, LTOK, CCH);
        sgemm_kernel<false, false, true><<<g, blk>>>(g_w, CCH, 0, x, LTOK, sX,
                                                     p_g, LTOK, sP, g_b,
                                                     CIN, LTOK, CCH);
    }
    // 2) f = theta^T @ phi : (L x CI)·(CI x L)  -> (L x L)
    {
        dim3 g(LTOK / BN, LTOK / BM, NBAT);
        sgemm_kernel<true, false, false><<<g, blk>>>(p_theta, LTOK, sP, p_phi, LTOK, sP,
                                                     p_f, LTOK, sF, nullptr,
                                                     LTOK, LTOK, CIN);
    }
    // 3) row softmax of f
    softmax_kernel<<<NBAT * LTOK, 256>>>(p_f);

    // 4) y2 = softmax(f) @ g^T : (L x L)·(L x CI) -> (L x CI)
    {
        dim3 g(CIN / BN, LTOK / BM, NBAT);
        sgemm_kernel<false, true, false><<<g, blk>>>(p_f, LTOK, sF, p_g, LTOK, sP,
                                                     p_y2, CIN, sY, nullptr,
                                                     LTOK, CIN, LTOK);
    }
    // 5) w_y = Wz(C x CI) @ y2^T(CI x L) + b
    {
        dim3 g(LTOK / BN, CCH / BM, NBAT);
        sgemm_kernel<false, true, true><<<g, blk>>>(wz_w, CIN, 0, p_y2, CIN, sY,
                                                    p_wy, LTOK, sW, wz_b,
                                                    CCH, LTOK, CIN);
    }
    // 6) batch-norm statistics
    bn_stats_kernel<<<CCH, 256>>>(p_wy, p_mean, p_rstd);

    // 7) BN apply + residual
    {
        const size_t total4 = (size_t)NBAT * CCH * LTOK / 4;
        bn_apply_kernel<<<(unsigned)((total4 + 255) / 256), 256>>>(
            p_wy, x, gamma, beta, p_mean, p_rstd, out);
    }
}

// round 3
// speedup vs baseline: 1.9780x; 1.9780x over previous
#include <cuda_runtime.h>
#include <cuda_bf16.h>
#include <cstdint>
#include <cstddef>

#define LTOK 4096   // H*W tokens
#define CCH  512    // in channels
#define CIN  256    // inter channels
#define NBAT 4      // batch
#define EPSV 1e-5f

// ---------------- scratch (device globals: no runtime allocation) ----------
__device__ float d_theta[(size_t)NBAT * CIN * LTOK];   // (CI, L) per batch
__device__ float d_phi  [(size_t)NBAT * CIN * LTOK];   // (CI, L)
__device__ float d_gbuf [(size_t)NBAT * CIN * LTOK];   // (CI, L)
__device__ float d_f    [(size_t)NBAT * LTOK * LTOK];  // 268 MB attention
__device__ float d_y2   [(size_t)NBAT * LTOK * CIN];   // (L, CI)
__device__ float d_wy   [(size_t)NBAT * CCH * LTOK];   // (C, L)
__device__ float d_mean [CCH];
__device__ float d_rstd [CCH];

// =========================== helpers ========================================
// pack two fp32 into bf16x2 (lo -> low 16 bits, hi -> high 16 bits)
__device__ __forceinline__ uint32_t cvt2bf(float lo, float hi) {
    uint32_t r;
    asm("cvt.rn.bf16x2.f32 %0, %1, %2;" : "=r"(r) : "f"(hi), "f"(lo));
    return r;
}
// split (x,y) into bf16 hi-pair and bf16 lo-pair (exact residual)
__device__ __forceinline__ void split2(float x, float y, uint32_t& h, uint32_t& l) {
    h = cvt2bf(x, y);
    const float hx = __uint_as_float(h << 16);
    const float hy = __uint_as_float(h & 0xffff0000u);
    l = cvt2bf(x - hx, y - hy);
}
__device__ __forceinline__ void mma16816(float c[4], const uint32_t a[4],
                                         uint32_t b0, uint32_t b1) {
    asm volatile(
        "mma.sync.aligned.m16n8k16.row.col.f32.bf16.bf16.f32 "
        "{%0,%1,%2,%3}, {%4,%5,%6,%7}, {%8,%9}, {%0,%1,%2,%3};"
        : "+f"(c[0]), "+f"(c[1]), "+f"(c[2]), "+f"(c[3])
        : "r"(a[0]), "r"(a[1]), "r"(a[2]), "r"(a[3]), "r"(b0), "r"(b1));
}

// smem index: direct layout [outer(128)][kpair(16)] stride 20 (conflict-free frags)
//             scatter layout [kpair(16)][outer(128)] stride 136 (conflict-free frags,
//             perfectly coalesced STS.128 on the transpose store)
template<bool DIR>
__device__ __forceinline__ int sidx(int outer, int kp) {
    return DIR ? outer * 20 + kp : kp * 136 + outer;
}

// per-buffer u32 footprint: 4 matrices x 2560 u32 = 10240 u32 (40960 B)
constexpr int BUFU  = 10240;
constexpr int OFF_AH = 0, OFF_AL = 2560, OFF_BH = 5120, OFF_BL = 7680;
constexpr int SMEM_BYTES = 2 * BUFU * 4;   // 81920

// ============ bf16x3 split-precision GEMM: D(MxN) += A·B(+bias) =============
// ADIR: A stored M x K (else K x M).  BDIR: B stored N x K (else K x N).
// D row-major M x N. All dims multiples of 128; K multiple of 32.
template<bool ADIR, bool BDIR, bool BIAS>
__global__ void __launch_bounds__(256, 1)
gemm_bf16x3(const float* __restrict__ A, int lda, long long sA,
            const float* __restrict__ B, int ldb, long long sB,
            float*       __restrict__ D, int ldc, long long sD,
            const float* __restrict__ bias, int K)
{
    extern __shared__ uint32_t sm[];
    A += (size_t)blockIdx.z * sA;
    B += (size_t)blockIdx.z * sB;
    D += (size_t)blockIdx.z * sD;

    const int bm = blockIdx.y * 128;
    const int bn = blockIdx.x * 128;
    const int tid  = threadIdx.x;
    const int lane = tid & 31;
    const int wm = ((tid >> 5) & 3) * 32;   // warp M offset (4 warps in M)
    const int wn = (tid >> 7) * 64;         // warp N offset (2 warps in N)

    float acc[2][8][4];
#pragma unroll
    for (int a = 0; a < 2; a++)
#pragma unroll
        for (int b = 0; b < 8; b++)
#pragma unroll
            for (int c = 0; c < 4; c++) acc[a][b][c] = 0.f;

    float4 ra[4], rb[4];

    auto ldgA = [&](int k0) {
        if (ADIR) {
#pragma unroll
            for (int p = 0; p < 4; p++) {
                const int i = tid + p * 256;
                ra[p] = *(const float4*)&A[(size_t)(bm + (i >> 3)) * lda + k0 + (i & 7) * 4];
            }
        } else {
#pragma unroll
            for (int p = 0; p < 2; p++) {
                const int j = tid + p * 256;
                const int kp = j >> 5, m4 = (j & 31) * 4;
                ra[2 * p]     = *(const float4*)&A[(size_t)(k0 + 2 * kp)     * lda + bm + m4];
                ra[2 * p + 1] = *(const float4*)&A[(size_t)(k0 + 2 * kp + 1) * lda + bm + m4];
            }
        }
    };
    auto ldgB = [&](int k0) {
        if (BDIR) {
#pragma unroll
            for (int p = 0; p < 4; p++) {
                const int i = tid + p * 256;
                rb[p] = *(const float4*)&B[(size_t)(bn + (i >> 3)) * ldb + k0 + (i & 7) * 4];
            }
        } else {
#pragma unroll
            for (int p = 0; p < 2; p++) {
                const int j = tid + p * 256;
                const int kp = j >> 5, m4 = (j & 31) * 4;
                rb[2 * p]     = *(const float4*)&B[(size_t)(k0 + 2 * kp)     * ldb + bn + m4];
                rb[2 * p + 1] = *(const float4*)&B[(size_t)(k0 + 2 * kp + 1) * ldb + bn + m4];
            }
        }
    };
    auto stsA = [&](int buf) {
        uint32_t* hi = sm + buf * BUFU + OFF_AH;
        uint32_t* lo = sm + buf * BUFU + OFF_AL;
        if (ADIR) {
#pragma unroll
            for (int p = 0; p < 4; p++) {
                const int i = tid + p * 256;
                const int r = i >> 3, c2 = (i & 7) * 2;
                uint32_t h0, l0, h1, l1;
                split2(ra[p].x, ra[p].y, h0, l0);
                split2(ra[p].z, ra[p].w, h1, l1);
                hi[r * 20 + c2] = h0; hi[r * 20 + c2 + 1] = h1;
                lo[r * 20 + c2] = l0; lo[r * 20 + c2 + 1] = l1;
            }
        } else {
#pragma unroll
            for (int p = 0; p < 2; p++) {
                const int j = tid + p * 256;
                const int kp = j >> 5, m4 = (j & 31) * 4;
                const float* va = (const float*)&ra[2 * p];
                const float* vb = (const float*)&ra[2 * p + 1];
                uint4 H, L;
                split2(va[0], vb[0], H.x, L.x);
                split2(va[1], vb[1], H.y, L.y);
                split2(va[2], vb[2], H.z, L.z);
                split2(va[3], vb[3], H.w, L.w);
                *(uint4*)&hi[kp * 136 + m4] = H;
                *(uint4*)&lo[kp * 136 + m4] = L;
            }
        }
    };
    auto stsB = [&](int buf) {
        uint32_t* hi = sm + buf * BUFU + OFF_BH;
        uint32_t* lo = sm + buf * BUFU + OFF_BL;
        if (BDIR) {
#pragma unroll
            for (int p = 0; p < 4; p++) {
                const int i = tid + p * 256;
                const int r = i >> 3, c2 = (i & 7) * 2;
                uint32_t h0, l0, h1, l1;
                split2(rb[p].x, rb[p].y, h0, l0);
                split2(rb[p].z, rb[p].w, h1, l1);
                hi[r * 20 + c2] = h0; hi[r * 20 + c2 + 1] = h1;
                lo[r * 20 + c2] = l0; lo[r * 20 + c2 + 1] = l1;
            }
        } else {
#pragma unroll
            for (int p = 0; p < 2; p++) {
                const int j = tid + p * 256;
                const int kp = j >> 5, m4 = (j & 31) * 4;
                const float* va = (const float*)&rb[2 * p];
                const float* vb = (const float*)&rb[2 * p + 1];
                uint4 H, L;
                split2(va[0], vb[0], H.x, L.x);
                split2(va[1], vb[1], H.y, L.y);
                split2(va[2], vb[2], H.z, L.z);
                split2(va[3], vb[3], H.w, L.w);
                *(uint4*)&hi[kp * 136 + m4] = H;
                *(uint4*)&lo[kp * 136 + m4] = L;
            }
        }
    };

    const int KT = K / 32;
    ldgA(0); ldgB(0);

    for (int kt = 0; kt < KT; kt++) {
        const int buf = kt & 1;
        stsA(buf); stsB(buf);
        __syncthreads();
        if (kt + 1 < KT) { ldgA((kt + 1) * 32); ldgB((kt + 1) * 32); }

        const uint32_t* ah = sm + buf * BUFU + OFF_AH;
        const uint32_t* al = sm + buf * BUFU + OFF_AL;
        const uint32_t* bh = sm + buf * BUFU + OFF_BH;
        const uint32_t* bl = sm + buf * BUFU + OFF_BL;
#pragma unroll
        for (int s = 0; s < 2; s++) {
            const int kq = s * 8 + (lane & 3);
            uint32_t Ah[2][4], Al_[2][4];
#pragma unroll
            for (int mt = 0; mt < 2; mt++) {
                const int r = wm + mt * 16 + (lane >> 2);
                Ah[mt][0]  = ah[sidx<ADIR>(r,     kq)];
                Ah[mt][1]  = ah[sidx<ADIR>(r + 8, kq)];
                Ah[mt][2]  = ah[sidx<ADIR>(r,     kq + 4)];
                Ah[mt][3]  = ah[sidx<ADIR>(r + 8, kq + 4)];
                Al_[mt][0] = al[sidx<ADIR>(r,     kq)];
                Al_[mt][1] = al[sidx<ADIR>(r + 8, kq)];
                Al_[mt][2] = al[sidx<ADIR>(r,     kq + 4)];
                Al_[mt][3] = al[sidx<ADIR>(r + 8, kq + 4)];
            }
#pragma unroll
            for (int nt = 0; nt < 8; nt++) {
                const int n = wn + nt * 8 + (lane >> 2);
                const uint32_t b0h = bh[sidx<BDIR>(n, kq)];
                const uint32_t b1h = bh[sidx<BDIR>(n, kq + 4)];
                const uint32_t b0l = bl[sidx<BDIR>(n, kq)];
                const uint32_t b1l = bl[sidx<BDIR>(n, kq + 4)];
#pragma unroll
                for (int mt = 0; mt < 2; mt++) {
                    mma16816(acc[mt][nt], Ah[mt],  b0h, b1h);  // hi*hi
                    mma16816(acc[mt][nt], Ah[mt],  b0l, b1l);  // hi*lo
                    mma16816(acc[mt][nt], Al_[mt], b0h, b1h);  // lo*hi
                }
            }
        }
        __syncthreads();
    }

    // ---- epilogue: direct global stores ----
#pragma unroll
    for (int mt = 0; mt < 2; mt++) {
        const int r0 = bm + wm + mt * 16 + (lane >> 2);
        const float bv0 = BIAS ? bias[r0]     : 0.f;
        const float bv8 = BIAS ? bias[r0 + 8] : 0.f;
#pragma unroll
        for (int nt = 0; nt < 8; nt++) {
            const int c0 = bn + wn + nt * 8 + (lane & 3) * 2;
            float2 v0, v1;
            v0.x = acc[mt][nt][0] + bv0; v0.y = acc[mt][nt][1] + bv0;
            v1.x = acc[mt][nt][2] + bv8; v1.y = acc[mt][nt][3] + bv8;
            *(float2*)&D[(size_t)r0 * ldc + c0]       = v0;
            *(float2*)&D[(size_t)(r0 + 8) * ldc + c0] = v1;
        }
    }
}

// ---------------- row softmax over f (rows of 4096) -------------------------
__global__ __launch_bounds__(256)
void softmax_kernel(float* __restrict__ f)
{
    float* row = f + (size_t)blockIdx.x * LTOK;
    const int tid = threadIdx.x;

    float4 v[4];
    float m = -1e30f;
#pragma unroll
    for (int i = 0; i < 4; i++) {
        v[i] = *(const float4*)&row[tid * 4 + i * 1024];
        m = fmaxf(m, fmaxf(fmaxf(v[i].x, v[i].y), fmaxf(v[i].z, v[i].w)));
    }
#pragma unroll
    for (int o = 16; o; o >>= 1) m = fmaxf(m, __shfl_xor_sync(0xffffffffu, m, o));

    __shared__ float red[8];
    if ((tid & 31) == 0) red[tid >> 5] = m;
    __syncthreads();
    float gmax = -1e30f;
#pragma unroll
    for (int i = 0; i < 8; i++) gmax = fmaxf(gmax, red[i]);

    float s = 0.f;
#pragma unroll
    for (int i = 0; i < 4; i++) {
        v[i].x = __expf(v[i].x - gmax);
        v[i].y = __expf(v[i].y - gmax);
        v[i].z = __expf(v[i].z - gmax);
        v[i].w = __expf(v[i].w - gmax);
        s += v[i].x + v[i].y + v[i].z + v[i].w;
    }
#pragma unroll
    for (int o = 16; o; o >>= 1) s += __shfl_xor_sync(0xffffffffu, s, o);
    __syncthreads();
    if ((tid & 31) == 0) red[tid >> 5] = s;
    __syncthreads();
    float gsum = 0.f;
#pragma unroll
    for (int i = 0; i < 8; i++) gsum += red[i];
    const float inv = 1.f / gsum;

#pragma unroll
    for (int i = 0; i < 4; i++) {
        v[i].x *= inv; v[i].y *= inv; v[i].z *= inv; v[i].w *= inv;
        *(float4*)&row[tid * 4 + i * 1024] = v[i];
    }
}

// ---------------- batchnorm statistics ---------------------------------------
__global__ __launch_bounds__(256)
void bn_stats_kernel(const float* __restrict__ wy,
                     float* __restrict__ mean, float* __restrict__ rstd)
{
    const int c = blockIdx.x;
    float s = 0.f, s2 = 0.f;
    for (int idx = threadIdx.x; idx < NBAT * LTOK; idx += 256) {
        const int n = idx >> 12;
        const int l = idx & (LTOK - 1);
        const float v = wy[((size_t)n * CCH + c) * LTOK + l];
        s += v; s2 += v * v;
    }
#pragma unroll
    for (int o = 16; o; o >>= 1) {
        s  += __shfl_xor_sync(0xffffffffu, s, o);
        s2 += __shfl_xor_sync(0xffffffffu, s2, o);
    }
    __shared__ float rs[8], rs2[8];
    if ((threadIdx.x & 31) == 0) { rs[threadIdx.x >> 5] = s; rs2[threadIdx.x >> 5] = s2; }
    __syncthreads();
    if (threadIdx.x == 0) {
        float S = 0.f, S2 = 0.f;
#pragma unroll
        for (int i = 0; i < 8; i++) { S += rs[i]; S2 += rs2[i]; }
        const float inv_cnt = 1.f / (float)(NBAT * LTOK);
        const float mu = S * inv_cnt;
        const float var = S2 * inv_cnt - mu * mu;
        mean[c] = mu;
        rstd[c] = rsqrtf(var + EPSV);
    }
}

// ---------------- BN apply + residual ---------------------------------------
__global__ __launch_bounds__(256)
void bn_apply_kernel(const float* __restrict__ wy, const float* __restrict__ x,
                     const float* __restrict__ gamma, const float* __restrict__ beta,
                     const float* __restrict__ mean, const float* __restrict__ rstd,
                     float* __restrict__ out)
{
    const size_t i = (size_t)blockIdx.x * blockDim.x + threadIdx.x;
    const size_t base = i * 4;
    if (base >= (size_t)NBAT * CCH * LTOK) return;
    const int c = (int)((base >> 12) & (CCH - 1));
    const float4 w  = *(const float4*)(wy + base);
    const float4 xv = *(const float4*)(x + base);
    const float mu = mean[c];
    const float sc = rstd[c] * gamma[c];
    const float be = beta[c];
    float4 o;
    o.x = (w.x - mu) * sc + be + xv.x;
    o.y = (w.y - mu) * sc + be + xv.y;
    o.z = (w.z - mu) * sc + be + xv.z;
    o.w = (w.w - mu) * sc + be + xv.w;
    *(float4*)(out + base) = o;
}

// ---------------- launch ------------------------------------------------------
extern "C" void kernel_launch(void* const* d_in, const int* in_sizes, int n_in,
                              void* d_out, int out_size)
{
    const float* x     = (const float*)d_in[0];
    const float* g_w   = (const float*)d_in[1];
    const float* g_b   = (const float*)d_in[2];
    const float* th_w  = (const float*)d_in[3];
    const float* th_b  = (const float*)d_in[4];
    const float* ph_w  = (const float*)d_in[5];
    const float* ph_b  = (const float*)d_in[6];
    const float* wz_w  = (const float*)d_in[7];
    const float* wz_b  = (const float*)d_in[8];
    const float* gamma = (const float*)d_in[9];
    const float* beta  = (const float*)d_in[10];
    float* out = (float*)d_out;

    float *p_th, *p_ph, *p_g, *p_f, *p_y2, *p_wy, *p_mean, *p_rstd;
    cudaGetSymbolAddress((void**)&p_th,   d_theta);
    cudaGetSymbolAddress((void**)&p_ph,   d_phi);
    cudaGetSymbolAddress((void**)&p_g,    d_gbuf);
    cudaGetSymbolAddress((void**)&p_f,    d_f);
    cudaGetSymbolAddress((void**)&p_y2,   d_y2);
    cudaGetSymbolAddress((void**)&p_wy,   d_wy);
    cudaGetSymbolAddress((void**)&p_mean, d_mean);
    cudaGetSymbolAddress((void**)&p_rstd, d_rstd);

    cudaFuncSetAttribute(gemm_bf16x3<true,  false, true >, cudaFuncAttributeMaxDynamicSharedMemorySize, SMEM_BYTES);
    cudaFuncSetAttribute(gemm_bf16x3<false, false, false>, cudaFuncAttributeMaxDynamicSharedMemorySize, SMEM_BYTES);
    cudaFuncSetAttribute(gemm_bf16x3<true,  true,  false>, cudaFuncAttributeMaxDynamicSharedMemorySize, SMEM_BYTES);
    cudaFuncSetAttribute(gemm_bf16x3<true,  true,  true >, cudaFuncAttributeMaxDynamicSharedMemorySize, SMEM_BYTES);

    const dim3 blk(256);
    const long long sX = (long long)CCH * LTOK;    // x batch stride
    const long long sP = (long long)CIN * LTOK;    // theta/phi/g stride
    const long long sF = (long long)LTOK * LTOK;   // f stride
    const long long sY = (long long)LTOK * CIN;    // y2 stride
    const long long sW = (long long)CCH * LTOK;    // wy stride

    // 1) projections: theta/phi/g (CI x L) = W(CI x C) @ x(C x L) + b
    //    A = W (M x K direct), B = x (K x N -> scatter), bias per row.
    {
        dim3 g(LTOK / 128, CIN / 128, NBAT);
        gemm_bf16x3<true, false, true><<<g, blk, SMEM_BYTES>>>(
            th_w, CCH, 0, x, LTOK, sX, p_th, LTOK, sP, th_b, CCH);
        gemm_bf16x3<true, false, true><<<g, blk, SMEM_BYTES>>>(
            ph_w, CCH, 0, x, LTOK, sX, p_ph, LTOK, sP, ph_b, CCH);
        gemm_bf16x3<true, false, true><<<g, blk, SMEM_BYTES>>>(
            g_w, CCH, 0, x, LTOK, sX, p_g, LTOK, sP, g_b, CCH);
    }
    // 2) f(L x L) = theta^T @ phi : A = theta (K x M scatter), B = phi (K x N scatter)
    {
        dim3 g(LTOK / 128, LTOK / 128, NBAT);
        gemm_bf16x3<false, false, false><<<g, blk, SMEM_BYTES>>>(
            p_th, LTOK, sP, p_ph, LTOK, sP, p_f, LTOK, sF, nullptr, CIN);
    }
    // 3) row softmax
    softmax_kernel<<<NBAT * LTOK, 256>>>(p_f);
    // 4) y2(L x CI) = softmax(f) @ g^T : A = f (M x K direct), B = g (N x K direct)
    {
        dim3 g(CIN / 128, LTOK / 128, NBAT);
        gemm_bf16x3<true, true, false><<<g, blk, SMEM_BYTES>>>(
            p_f, LTOK, sF, p_g, LTOK, sP, p_y2, CIN, sY, nullptr, LTOK);
    }
    // 5) w_y(C x L) = Wz @ y2^T : A = wz_w (M x K direct), B = y2 (N x K direct), bias
    {
        dim3 g(LTOK / 128, CCH / 128, NBAT);
        gemm_bf16x3<true, true, true><<<g, blk, SMEM_BYTES>>>(
            wz_w, CIN, 0, p_y2, CIN, sY, p_wy, LTOK, sW, wz_b, CIN);
    }
    // 6) BN stats
    bn_stats_kernel<<<CCH, 256>>>(p_wy, p_mean, p_rstd);
    // 7) BN apply + residual
    {
        const size_t total4 = (size_t)NBAT * CCH * LTOK / 4;
        bn_apply_kernel<<<(unsigned)((total4 + 255) / 256), 256>>>(
            p_wy, x, gamma, beta, p_mean, p_rstd, out);
    }
}